// round 2
// baseline (speedup 1.0000x reference)
#include <cuda_runtime.h>
#include <cuda_bf16.h>

#define N_NODES 10000
#define N_EDGES 100000
#define HIDDEN  128
#define WN      1600
#define IN_DIM  56

// ---- scratch (static __device__; no allocation at runtime) ----
__device__ float g_H[(size_t)N_EDGES * HIDDEN];   // 51.2 MB
__device__ float g_W[(size_t)N_EDGES * WN];       // 640 MB
__device__ float g_num[(size_t)N_NODES * IN_DIM]; // segment sums
__device__ float g_cnt[N_NODES];
__device__ float g_stats[72];                     // sum_s[32], sum_s2[32], sum_v2[8]

// ------------------------------------------------------------------
// zero accumulators (must run every launch; graph replays)
// ------------------------------------------------------------------
__global__ void zero_kernel() {
    int i = blockIdx.x * blockDim.x + threadIdx.x;
    const int t0 = N_NODES * IN_DIM;            // 560000
    const int t1 = t0 + N_NODES;                // 570000
    const int t2 = t1 + 72;                     // 570072
    if (i < t0)       g_num[i] = 0.f;
    else if (i < t1)  g_cnt[i - t0] = 0.f;
    else if (i < t2)  g_stats[i - t1] = 0.f;
}

// ------------------------------------------------------------------
// SGEMM  C = act(A@B + bias)   A:[M,K] row-major, B:[K,N] row-major
// MODE 0: A = edge_attr arg, C = g_H, ReLU
// MODE 1: A = g_H,           C = g_W, no act
// BM=BN=128, BK=16, 256 threads, 8x8 per thread
// ------------------------------------------------------------------
template<int MODE>
__global__ void sgemm_kernel(const float* __restrict__ Ain,
                             const float* __restrict__ B,
                             const float* __restrict__ bias,
                             int M, int N, int K) {
    const float* A = (MODE == 0) ? Ain : g_H;
    float*       C = (MODE == 0) ? g_H : g_W;

    __shared__ float As[16][132];   // transposed, padded (16B-aligned rows)
    __shared__ float Bs[16][128];

    const int bm = blockIdx.y * 128;
    const int bn = blockIdx.x * 128;
    const int tid = threadIdx.x;          // 0..255
    const int tx = tid & 15;              // col group
    const int ty = tid >> 4;              // row group
    const int row0 = ty * 8;
    const int col0 = tx * 8;

    float acc[8][8];
    #pragma unroll
    for (int i = 0; i < 8; i++)
        #pragma unroll
        for (int j = 0; j < 8; j++) acc[i][j] = 0.f;

    for (int k0 = 0; k0 < K; k0 += 16) {
        // load A tile 128x16 (512 float4, 2 per thread), store transposed
        #pragma unroll
        for (int l = 0; l < 2; l++) {
            int f  = tid + l * 256;
            int r  = f >> 2;            // 0..127
            int c4 = (f & 3) * 4;       // 0,4,8,12
            int gr = bm + r;
            float4 v = make_float4(0.f, 0.f, 0.f, 0.f);
            if (gr < M)
                v = *reinterpret_cast<const float4*>(&A[(size_t)gr * K + k0 + c4]);
            As[c4 + 0][r] = v.x; As[c4 + 1][r] = v.y;
            As[c4 + 2][r] = v.z; As[c4 + 3][r] = v.w;
        }
        // load B tile 16x128 (512 float4, 2 per thread)
        #pragma unroll
        for (int l = 0; l < 2; l++) {
            int f  = tid + l * 256;
            int r  = f >> 5;            // 0..15
            int c4 = (f & 31) * 4;      // 0..124
            float4 v = make_float4(0.f, 0.f, 0.f, 0.f);
            if (bn + c4 < N)
                v = *reinterpret_cast<const float4*>(&B[(size_t)(k0 + r) * N + bn + c4]);
            *reinterpret_cast<float4*>(&Bs[r][c4]) = v;
        }
        __syncthreads();

        #pragma unroll
        for (int k = 0; k < 16; k++) {
            float ra[8], rb[8];
            *reinterpret_cast<float4*>(&ra[0]) = *reinterpret_cast<const float4*>(&As[k][row0]);
            *reinterpret_cast<float4*>(&ra[4]) = *reinterpret_cast<const float4*>(&As[k][row0 + 4]);
            *reinterpret_cast<float4*>(&rb[0]) = *reinterpret_cast<const float4*>(&Bs[k][col0]);
            *reinterpret_cast<float4*>(&rb[4]) = *reinterpret_cast<const float4*>(&Bs[k][col0 + 4]);
            #pragma unroll
            for (int i = 0; i < 8; i++)
                #pragma unroll
                for (int j = 0; j < 8; j++)
                    acc[i][j] += ra[i] * rb[j];
        }
        __syncthreads();
    }

    // epilogue
    #pragma unroll
    for (int i = 0; i < 8; i++) {
        int gr = bm + row0 + i;
        if (gr >= M) continue;
        #pragma unroll
        for (int j = 0; j < 8; j += 4) {
            int gc = bn + col0 + j;
            if (gc >= N) continue;
            float4 v;
            v.x = acc[i][j + 0] + bias[gc + 0];
            v.y = acc[i][j + 1] + bias[gc + 1];
            v.z = acc[i][j + 2] + bias[gc + 2];
            v.w = acc[i][j + 3] + bias[gc + 3];
            if (MODE == 0) {
                v.x = fmaxf(v.x, 0.f); v.y = fmaxf(v.y, 0.f);
                v.z = fmaxf(v.z, 0.f); v.w = fmaxf(v.w, 0.f);
            }
            *reinterpret_cast<float4*>(&C[(size_t)gr * N + gc]) = v;
        }
    }
}

// ------------------------------------------------------------------
// Per-edge tensor product + scatter (one warp per edge)
// W layout per edge: [0,1024) w00[u32,w32]; [1024,1280) w11[u8,w32];
//                    [1280,1536) w01[u32,w8]; [1536,1600) w10[u8,w8]
// ------------------------------------------------------------------
__global__ void tp_kernel(const float* __restrict__ node_attr,
                          const int*   __restrict__ edge_index,
                          const float* __restrict__ edge_sh) {
    int e = blockIdx.x * (blockDim.x >> 5) + (threadIdx.x >> 5);
    if (e >= N_EDGES) return;
    const int lane = threadIdx.x & 31;
    const int src = edge_index[e];
    const int dst = edge_index[N_EDGES + e];
    const float* x  = node_attr + (size_t)dst * IN_DIM;
    const float* we = g_W + (size_t)e * WN;
    const float y0  = edge_sh[e * 4 + 0];
    const float y1x = edge_sh[e * 4 + 1];
    const float y1y = edge_sh[e * 4 + 2];
    const float y1z = edge_sh[e * 4 + 3];
    const float alpha = 0.15811388300841897f;     // 1/sqrt(40)
    const float inv_sqrt3 = 0.57735026918962576f;

    // out0 : lane = w (0..31)
    float acc0 = 0.f;
    {
        const int w = lane;
        #pragma unroll
        for (int u = 0; u < 32; u++)
            acc0 += (x[u] * y0) * we[u * 32 + w];
        #pragma unroll
        for (int u = 0; u < 8; u++) {
            float d = x[32 + u * 3 + 0] * y1x
                    + x[32 + u * 3 + 1] * y1y
                    + x[32 + u * 3 + 2] * y1z;
            acc0 += inv_sqrt3 * d * we[1024 + u * 32 + w];
        }
        acc0 *= alpha;
    }

    // out1 : lanes 0..23, lane = w*3 + m
    float acc1 = 0.f;
    if (lane < 24) {
        const int w = lane / 3, m = lane % 3;
        float t = 0.f;
        #pragma unroll
        for (int u = 0; u < 32; u++)
            t += x[u] * we[1280 + u * 8 + w];
        float d = 0.f;
        #pragma unroll
        for (int u = 0; u < 8; u++)
            d += x[32 + u * 3 + m] * we[1536 + u * 8 + w];
        const float ym = edge_sh[e * 4 + 1 + m];
        acc1 = alpha * (t * ym + y0 * d);
    }

    atomicAdd(&g_num[(size_t)src * IN_DIM + lane], acc0);
    if (lane < 24) atomicAdd(&g_num[(size_t)src * IN_DIM + 32 + lane], acc1);
    if (lane == 0) atomicAdd(&g_cnt[src], 1.0f);
}

// ------------------------------------------------------------------
// finalize 1: out_pre = num/max(cnt,1) + node_attr  (staged into d_out)
//             + accumulate BN statistics
// one thread per node, 256 threads/block
// ------------------------------------------------------------------
__global__ void finalize1_kernel(const float* __restrict__ node_attr,
                                 float* __restrict__ staged) {
    __shared__ float s_stats[72];
    const int t = threadIdx.x;
    if (t < 72) s_stats[t] = 0.f;
    __syncthreads();

    const int n = blockIdx.x * blockDim.x + t;
    const bool valid = (n < N_NODES);
    float ic = 0.f;
    if (valid) ic = 1.f / fmaxf(g_cnt[n], 1.f);
    const int lane = t & 31;

    // scalar channels 0..31: need sum and sum^2
    for (int j = 0; j < 32; j++) {
        float o = 0.f;
        if (valid) {
            o = g_num[(size_t)n * IN_DIM + j] * ic + node_attr[(size_t)n * IN_DIM + j];
            staged[(size_t)n * IN_DIM + j] = o;
        }
        float so = o, so2 = o * o;
        #pragma unroll
        for (int off = 16; off > 0; off >>= 1) {
            so  += __shfl_down_sync(0xffffffffu, so,  off);
            so2 += __shfl_down_sync(0xffffffffu, so2, off);
        }
        if (lane == 0) {
            atomicAdd(&s_stats[j], so);
            atomicAdd(&s_stats[32 + j], so2);
        }
    }
    // vector channels 32..55: need sum^2 per u = (j-32)/3
    for (int j = 32; j < 56; j++) {
        float o = 0.f;
        if (valid) {
            o = g_num[(size_t)n * IN_DIM + j] * ic + node_attr[(size_t)n * IN_DIM + j];
            staged[(size_t)n * IN_DIM + j] = o;
        }
        float so2 = o * o;
        #pragma unroll
        for (int off = 16; off > 0; off >>= 1)
            so2 += __shfl_down_sync(0xffffffffu, so2, off);
        if (lane == 0)
            atomicAdd(&s_stats[64 + (j - 32) / 3], so2);
    }
    __syncthreads();
    if (t < 72) atomicAdd(&g_stats[t], s_stats[t]);
}

// ------------------------------------------------------------------
// finalize 2: batch norm applied in place on d_out
// ------------------------------------------------------------------
__global__ void finalize2_kernel(const float* __restrict__ bn_w_s,
                                 const float* __restrict__ bn_w_v,
                                 const float* __restrict__ bn_b_s,
                                 float* __restrict__ out) {
    const int idx = blockIdx.x * blockDim.x + threadIdx.x;
    if (idx >= N_NODES * IN_DIM) return;
    const int j = idx % IN_DIM;
    const float x = out[idx];
    const float invN = 1.0f / (float)N_NODES;
    if (j < 32) {
        float mean = g_stats[j] * invN;
        float var  = g_stats[32 + j] * invN - mean * mean;
        out[idx] = (x - mean) * rsqrtf(var + 1e-5f) * bn_w_s[j] + bn_b_s[j];
    } else {
        int u = (j - 32) / 3;
        float vn = g_stats[64 + u] * invN * (1.0f / 3.0f);
        out[idx] = x * rsqrtf(vn + 1e-5f) * bn_w_v[u];
    }
}

// ------------------------------------------------------------------
extern "C" void kernel_launch(void* const* d_in, const int* in_sizes, int n_in,
                              void* d_out, int out_size) {
    const float* node_attr = (const float*)d_in[0];
    const int*   edge_index = (const int*)d_in[1];
    const float* edge_attr = (const float*)d_in[2];
    const float* edge_sh   = (const float*)d_in[3];
    const float* fc1_w     = (const float*)d_in[4];
    const float* fc1_b     = (const float*)d_in[5];
    const float* fc2_w     = (const float*)d_in[6];
    const float* fc2_b     = (const float*)d_in[7];
    const float* bn_w_s    = (const float*)d_in[8];
    const float* bn_w_v    = (const float*)d_in[9];
    const float* bn_b_s    = (const float*)d_in[10];
    float* out = (float*)d_out;

    // 0) zero accumulators
    zero_kernel<<<(570072 + 255) / 256, 256>>>();

    // 1) H = relu(edge_attr @ fc1_w + fc1_b)   [1e5,128]
    {
        dim3 grid(1, (N_EDGES + 127) / 128);
        sgemm_kernel<0><<<grid, 256>>>(edge_attr, fc1_w, fc1_b, N_EDGES, HIDDEN, HIDDEN);
    }
    // 2) W = H @ fc2_w + fc2_b                 [1e5,1600]
    {
        dim3 grid((WN + 127) / 128, (N_EDGES + 127) / 128);
        sgemm_kernel<1><<<grid, 256>>>(nullptr, fc2_w, fc2_b, N_EDGES, WN, HIDDEN);
    }
    // 3) per-edge tensor product + scatter into node accumulators
    tp_kernel<<<(N_EDGES + 7) / 8, 256>>>(node_attr, edge_index, edge_sh);

    // 4) segment mean + residual + BN stats
    finalize1_kernel<<<(N_NODES + 255) / 256, 256>>>(node_attr, out);

    // 5) batch norm
    finalize2_kernel<<<(N_NODES * IN_DIM + 255) / 256, 256>>>(bn_w_s, bn_w_v, bn_b_s, out);
}

// round 7
// speedup vs baseline: 2.0143x; 2.0143x over previous
#include <cuda_runtime.h>
#include <cuda_bf16.h>
#include <stdint.h>

#define N_NODES 10000
#define N_EDGES 100000
#define HIDDEN  128
#define WN      1600
#define IN_DIM  56
#define M_TILES ((N_EDGES + 127) / 128)   // 782
#define WN_PAD  1664                      // 13 * 128

// ---- scratch (static __device__; no allocation at runtime) ----
__device__ __nv_bfloat16 g_Hhi[(size_t)N_EDGES * HIDDEN];   // 25.6 MB
__device__ __nv_bfloat16 g_Hlo[(size_t)N_EDGES * HIDDEN];   // 25.6 MB
__device__ __nv_bfloat16 g_Bhi[(size_t)WN_PAD * HIDDEN];    // B^T hi [n][k]
__device__ __nv_bfloat16 g_Blo[(size_t)WN_PAD * HIDDEN];    // B^T lo [n][k]
__device__ float g_num[(size_t)N_NODES * IN_DIM];
__device__ float g_cnt[N_NODES];
__device__ float g_stats[72];

// ==================================================================
// mma.sync m16n8k16 bf16 (HMMA path; valid on plain sm_103 target)
// ==================================================================
__device__ __forceinline__ void mma16816(float* c, const uint32_t* a,
                                         uint32_t b0, uint32_t b1) {
    asm volatile(
        "mma.sync.aligned.m16n8k16.row.col.f32.bf16.bf16.f32 "
        "{%0,%1,%2,%3}, {%4,%5,%6,%7}, {%8,%9}, {%0,%1,%2,%3};"
        : "+f"(c[0]), "+f"(c[1]), "+f"(c[2]), "+f"(c[3])
        : "r"(a[0]), "r"(a[1]), "r"(a[2]), "r"(a[3]), "r"(b0), "r"(b1));
}

// ==================================================================
// zero accumulators (every replay)
// ==================================================================
__global__ void zero_kernel() {
    int i = blockIdx.x * blockDim.x + threadIdx.x;
    const int t0 = N_NODES * IN_DIM;
    const int t1 = t0 + N_NODES;
    const int t2 = t1 + 72;
    if (i < t0)       g_num[i] = 0.f;
    else if (i < t1)  g_cnt[i - t0] = 0.f;
    else if (i < t2)  g_stats[i - t1] = 0.f;
}

// ==================================================================
// prep B^T split bf16:  g_B{hi,lo}[n][k] = split(fc2_w[k][n]); n>=WN zero
// ==================================================================
__global__ void prepB_kernel(const float* __restrict__ fc2_w) {
    int i = blockIdx.x * blockDim.x + threadIdx.x;
    if (i >= WN_PAD * HIDDEN) return;
    int n = i >> 7, k = i & 127;
    float v = (n < WN) ? fc2_w[(size_t)k * WN + n] : 0.f;
    __nv_bfloat16 hi = __float2bfloat16(v);
    __nv_bfloat16 lo = __float2bfloat16(v - __bfloat162float(hi));
    g_Bhi[(size_t)n * HIDDEN + k] = hi;
    g_Blo[(size_t)n * HIDDEN + k] = lo;
}

// ==================================================================
// GEMM1 (fp32): H = relu(edge_attr @ fc1_w + b) -> split bf16 hi/lo
// ==================================================================
__global__ void sgemm1_kernel(const float* __restrict__ A,
                              const float* __restrict__ B,
                              const float* __restrict__ bias) {
    const int M = N_EDGES, N = HIDDEN, K = HIDDEN;
    __shared__ float As[16][132];
    __shared__ float Bs[16][128];

    const int bm = blockIdx.y * 128;
    const int tid = threadIdx.x;
    const int tx = tid & 15, ty = tid >> 4;
    const int row0 = ty * 8, col0 = tx * 8;

    float acc[8][8];
    #pragma unroll
    for (int i = 0; i < 8; i++)
        #pragma unroll
        for (int j = 0; j < 8; j++) acc[i][j] = 0.f;

    for (int k0 = 0; k0 < K; k0 += 16) {
        #pragma unroll
        for (int l = 0; l < 2; l++) {
            int f = tid + l * 256;
            int r = f >> 2, c4 = (f & 3) * 4;
            int gr = bm + r;
            float4 v = make_float4(0.f, 0.f, 0.f, 0.f);
            if (gr < M) v = *reinterpret_cast<const float4*>(&A[(size_t)gr * K + k0 + c4]);
            As[c4 + 0][r] = v.x; As[c4 + 1][r] = v.y;
            As[c4 + 2][r] = v.z; As[c4 + 3][r] = v.w;
        }
        #pragma unroll
        for (int l = 0; l < 2; l++) {
            int f = tid + l * 256;
            int r = f >> 5, c4 = (f & 31) * 4;
            float4 v = *reinterpret_cast<const float4*>(&B[(size_t)(k0 + r) * N + c4]);
            *reinterpret_cast<float4*>(&Bs[r][c4]) = v;
        }
        __syncthreads();
        #pragma unroll
        for (int k = 0; k < 16; k++) {
            float ra[8], rb[8];
            *reinterpret_cast<float4*>(&ra[0]) = *reinterpret_cast<const float4*>(&As[k][row0]);
            *reinterpret_cast<float4*>(&ra[4]) = *reinterpret_cast<const float4*>(&As[k][row0 + 4]);
            *reinterpret_cast<float4*>(&rb[0]) = *reinterpret_cast<const float4*>(&Bs[k][col0]);
            *reinterpret_cast<float4*>(&rb[4]) = *reinterpret_cast<const float4*>(&Bs[k][col0 + 4]);
            #pragma unroll
            for (int i = 0; i < 8; i++)
                #pragma unroll
                for (int j = 0; j < 8; j++) acc[i][j] += ra[i] * rb[j];
        }
        __syncthreads();
    }
    #pragma unroll
    for (int i = 0; i < 8; i++) {
        int gr = bm + row0 + i;
        if (gr >= M) continue;
        #pragma unroll
        for (int j = 0; j < 8; j++) {
            int gc = col0 + j;
            float v = fmaxf(acc[i][j] + bias[gc], 0.f);
            __nv_bfloat16 hi = __float2bfloat16(v);
            __nv_bfloat16 lo = __float2bfloat16(v - __bfloat162float(hi));
            g_Hhi[(size_t)gr * 128 + gc] = hi;
            g_Hlo[(size_t)gr * 128 + gc] = lo;
        }
    }
}

// ==================================================================
// FUSED: W = H @ fc2_w + b (mma.sync bf16-split) -> TP -> scatter
// 1 CTA = 128 edges, 256 threads (8 warps). 13 N-tiles of 128 cols.
// Warp w owns output rows [w*16, w*16+16), all 128 cols of each tile.
// SMEM (bf16 tiles padded to stride 136 elems for conflict-free LDS):
//   Ahi 34816 | Alo 34816 | Bhi 34816 | Blo 34816 | X 34816 | bias 512
// ==================================================================
#define AB_STRIDE 136
#define SM_AHI  0
#define SM_ALO  34816
#define SM_BHI  69632
#define SM_BLO  104448
#define SM_X    139264
#define X_STRIDE 68
#define SM_BIAS 174080
#define SMEM_SZ 174592

__global__ void __launch_bounds__(256, 1)
gemm2_tp_kernel(const float* __restrict__ node_attr,
                const int*   __restrict__ edge_index,
                const float* __restrict__ edge_sh,
                const float* __restrict__ fc2_b) {
    extern __shared__ char smem[];
    __nv_bfloat16* Ahi = reinterpret_cast<__nv_bfloat16*>(smem + SM_AHI);
    __nv_bfloat16* Alo = reinterpret_cast<__nv_bfloat16*>(smem + SM_ALO);
    __nv_bfloat16* Bhi = reinterpret_cast<__nv_bfloat16*>(smem + SM_BHI);
    __nv_bfloat16* Blo = reinterpret_cast<__nv_bfloat16*>(smem + SM_BLO);
    float* xss   = reinterpret_cast<float*>(smem + SM_X);
    float* biass = reinterpret_cast<float*>(smem + SM_BIAS);

    const int tid  = threadIdx.x;
    const int warp = tid >> 5;
    const int lane = tid & 31;
    const int gid  = lane >> 2;     // 0..7
    const int qid  = lane & 3;      // 0..3
    const int bm   = blockIdx.x * 128;

    // --- load A panels (Hhi/Hlo rows bm..bm+127) ---
    for (int i = tid; i < 2048; i += 256) {
        int r = i >> 4, q = i & 15;
        int gr = bm + r;
        uint4 vh = make_uint4(0u, 0u, 0u, 0u), vl = vh;
        if (gr < N_EDGES) {
            vh = reinterpret_cast<const uint4*>(g_Hhi + (size_t)gr * 128)[q];
            vl = reinterpret_cast<const uint4*>(g_Hlo + (size_t)gr * 128)[q];
        }
        *reinterpret_cast<uint4*>(Ahi + r * AB_STRIDE + q * 8) = vh;
        *reinterpret_cast<uint4*>(Alo + r * AB_STRIDE + q * 8) = vl;
    }

    // --- per-edge features + metadata into SMEM ---
    if (tid < 128) {
        const int e = bm + tid;
        const bool valid = (e < N_EDGES);
        float* xr = xss + tid * X_STRIDE;
        int dst = valid ? edge_index[N_EDGES + e] : 0;
        for (int j = 0; j < IN_DIM; j++)
            xr[j] = valid ? node_attr[(size_t)dst * IN_DIM + j] : 0.f;
        float y0 = 0.f, yx = 0.f, yy = 0.f, yz = 0.f;
        int src = 0;
        if (valid) {
            src = edge_index[e];
            y0 = edge_sh[e * 4 + 0];
            yx = edge_sh[e * 4 + 1];
            yy = edge_sh[e * 4 + 2];
            yz = edge_sh[e * 4 + 3];
        }
        xr[56] = y0; xr[57] = yx; xr[58] = yy; xr[59] = yz;
        reinterpret_cast<int*>(xr)[60] = src;
        reinterpret_cast<int*>(xr)[61] = valid ? 1 : 0;
    }
    __syncthreads();

    const float alpha = 0.15811388300841897f;        // 1/sqrt(40)
    const float cB    = alpha * 0.57735026918962576f; // alpha/sqrt(3)

    // per-thread TP accumulators (each (edge,channel) owned by one thread)
    float out0[16];   // [e][ (n8&3)*2 + p ] -> w = (n8&3)*8 + qid*2 + p
    float out1[12];   // [e][p][m]           -> w8 = qid*2 + p
    float s1[4];      // [e][p]
    #pragma unroll
    for (int i = 0; i < 16; i++) out0[i] = 0.f;
    #pragma unroll
    for (int i = 0; i < 12; i++) out1[i] = 0.f;
    #pragma unroll
    for (int i = 0; i < 4; i++)  s1[i] = 0.f;

    const int lr0 = warp * 16 + gid;      // local edge row (e index 0)
    const float* xr0 = xss + lr0 * X_STRIDE;
    const float* xr1 = xss + (lr0 + 8) * X_STRIDE;

    // --- main loop over 13 N-tiles ---
    for (int nt = 0; nt < 13; nt++) {
        const int n0 = nt * 128;
        // load B tile (Bhi/Blo rows n0..n0+127)
        for (int i = tid; i < 2048; i += 256) {
            int r = i >> 4, q = i & 15;
            uint4 vh = reinterpret_cast<const uint4*>(g_Bhi + (size_t)(n0 + r) * 128)[q];
            uint4 vl = reinterpret_cast<const uint4*>(g_Blo + (size_t)(n0 + r) * 128)[q];
            *reinterpret_cast<uint4*>(Bhi + r * AB_STRIDE + q * 8) = vh;
            *reinterpret_cast<uint4*>(Blo + r * AB_STRIDE + q * 8) = vl;
        }
        if (tid < 128) {
            int n = n0 + tid;
            biass[tid] = (n < WN) ? fc2_b[n] : 0.f;
        }
        __syncthreads();

        // MMA: acc = Ahi*Bhi + Ahi*Blo + Alo*Bhi  (K=128, 8 k-steps)
        float acc[16][4];
        #pragma unroll
        for (int n8 = 0; n8 < 16; n8++)
            #pragma unroll
            for (int i = 0; i < 4; i++) acc[n8][i] = 0.f;

        #pragma unroll
        for (int ks = 0; ks < 8; ks++) {
            const int kk = ks * 16;
            const int ra = lr0 * AB_STRIDE + kk + qid * 2;
            uint32_t ah[4], al[4];
            ah[0] = *reinterpret_cast<const uint32_t*>(Ahi + ra);
            ah[1] = *reinterpret_cast<const uint32_t*>(Ahi + ra + 8 * AB_STRIDE);
            ah[2] = *reinterpret_cast<const uint32_t*>(Ahi + ra + 8);
            ah[3] = *reinterpret_cast<const uint32_t*>(Ahi + ra + 8 * AB_STRIDE + 8);
            al[0] = *reinterpret_cast<const uint32_t*>(Alo + ra);
            al[1] = *reinterpret_cast<const uint32_t*>(Alo + ra + 8 * AB_STRIDE);
            al[2] = *reinterpret_cast<const uint32_t*>(Alo + ra + 8);
            al[3] = *reinterpret_cast<const uint32_t*>(Alo + ra + 8 * AB_STRIDE + 8);
            #pragma unroll
            for (int n8 = 0; n8 < 16; n8++) {
                const int rb = (n8 * 8 + gid) * AB_STRIDE + kk + qid * 2;
                uint32_t bh0 = *reinterpret_cast<const uint32_t*>(Bhi + rb);
                uint32_t bh1 = *reinterpret_cast<const uint32_t*>(Bhi + rb + 8);
                uint32_t bl0 = *reinterpret_cast<const uint32_t*>(Blo + rb);
                uint32_t bl1 = *reinterpret_cast<const uint32_t*>(Blo + rb + 8);
                mma16816(acc[n8], ah, bh0, bh1);
                mma16816(acc[n8], ah, bl0, bl1);
                mma16816(acc[n8], al, bh0, bh1);
            }
        }

        // epilogue: contract this tile's W values with TP coefficients
        #pragma unroll
        for (int n8 = 0; n8 < 16; n8++) {
            if (nt == 12 && n8 >= 8) break;     // cols >= 1600: padding
            const int coll = n8 * 8 + qid * 2;
            const float bv0 = biass[coll], bv1 = biass[coll + 1];
            const int gblk = nt * 16 + n8;       // 8-col block index (0..207)

            #pragma unroll
            for (int e = 0; e < 2; e++) {
                const float* xr = e ? xr1 : xr0;
                const float v0 = acc[n8][e * 2 + 0] + bv0;
                const float v1 = acc[n8][e * 2 + 1] + bv1;
                if (gblk < 128) {                       // w00: u = gblk>>2
                    const int u = gblk >> 2;
                    const float coeff = xr[u] * (alpha * xr[56]);
                    const int o = e * 8 + (n8 & 3) * 2;
                    out0[o + 0] = fmaf(coeff, v0, out0[o + 0]);
                    out0[o + 1] = fmaf(coeff, v1, out0[o + 1]);
                } else if (gblk < 160) {                // w11: u = (gblk-128)>>2
                    const int u = (gblk - 128) >> 2;
                    const float du = xr[32 + u * 3 + 0] * xr[57]
                                   + xr[32 + u * 3 + 1] * xr[58]
                                   + xr[32 + u * 3 + 2] * xr[59];
                    const float coeff = du * cB;
                    const int o = e * 8 + (n8 & 3) * 2;
                    out0[o + 0] = fmaf(coeff, v0, out0[o + 0]);
                    out0[o + 1] = fmaf(coeff, v1, out0[o + 1]);
                } else if (gblk < 192) {                // w01: u = gblk-160
                    const float xu = xr[gblk - 160];
                    s1[e * 2 + 0] = fmaf(xu, v0, s1[e * 2 + 0]);
                    s1[e * 2 + 1] = fmaf(xu, v1, s1[e * 2 + 1]);
                } else {                                // w10: u = gblk-192
                    const int u = gblk - 192;
                    const float cy0 = alpha * xr[56];
                    const float x0 = xr[32 + u * 3 + 0] * cy0;
                    const float x1 = xr[32 + u * 3 + 1] * cy0;
                    const float x2 = xr[32 + u * 3 + 2] * cy0;
                    const int o = e * 6;
                    out1[o + 0] = fmaf(x0, v0, out1[o + 0]);
                    out1[o + 1] = fmaf(x1, v0, out1[o + 1]);
                    out1[o + 2] = fmaf(x2, v0, out1[o + 2]);
                    out1[o + 3] = fmaf(x0, v1, out1[o + 3]);
                    out1[o + 4] = fmaf(x1, v1, out1[o + 4]);
                    out1[o + 5] = fmaf(x2, v1, out1[o + 5]);
                }
            }
        }
        __syncthreads();   // B tile fully consumed by all warps
    }

    // fold s1 (w01 path) into out1 with y1[m], then scatter
    #pragma unroll
    for (int e = 0; e < 2; e++) {
        const float* xr = e ? xr1 : xr0;
        if (!reinterpret_cast<const int*>(xr)[61]) continue;
        const int src = reinterpret_cast<const int*>(xr)[60];
        const float yx = xr[57], yy = xr[58], yz = xr[59];
        #pragma unroll
        for (int p = 0; p < 2; p++) {
            const float sw = s1[e * 2 + p] * alpha;
            out1[e * 6 + p * 3 + 0] = fmaf(sw, yx, out1[e * 6 + p * 3 + 0]);
            out1[e * 6 + p * 3 + 1] = fmaf(sw, yy, out1[e * 6 + p * 3 + 1]);
            out1[e * 6 + p * 3 + 2] = fmaf(sw, yz, out1[e * 6 + p * 3 + 2]);
        }
        float* dstp = g_num + (size_t)src * IN_DIM;
        #pragma unroll
        for (int q = 0; q < 4; q++)
            #pragma unroll
            for (int p = 0; p < 2; p++) {
                const int w = q * 8 + qid * 2 + p;
                atomicAdd(&dstp[w], out0[e * 8 + q * 2 + p]);
            }
        #pragma unroll
        for (int p = 0; p < 2; p++) {
            const int w8 = qid * 2 + p;
            atomicAdd(&dstp[32 + w8 * 3 + 0], out1[e * 6 + p * 3 + 0]);
            atomicAdd(&dstp[32 + w8 * 3 + 1], out1[e * 6 + p * 3 + 1]);
            atomicAdd(&dstp[32 + w8 * 3 + 2], out1[e * 6 + p * 3 + 2]);
        }
        if (qid == 0) atomicAdd(&g_cnt[src], 1.0f);
    }
}

// ==================================================================
// finalize 1: out_pre = num/max(cnt,1) + node_attr, accumulate BN stats
// ==================================================================
__global__ void finalize1_kernel(const float* __restrict__ node_attr,
                                 float* __restrict__ staged) {
    __shared__ float s_stats[72];
    const int t = threadIdx.x;
    if (t < 72) s_stats[t] = 0.f;
    __syncthreads();

    const int n = blockIdx.x * blockDim.x + t;
    const bool valid = (n < N_NODES);
    float ic = 0.f;
    if (valid) ic = 1.f / fmaxf(g_cnt[n], 1.f);
    const int lane = t & 31;

    for (int j = 0; j < 32; j++) {
        float o = 0.f;
        if (valid) {
            o = g_num[(size_t)n * IN_DIM + j] * ic + node_attr[(size_t)n * IN_DIM + j];
            staged[(size_t)n * IN_DIM + j] = o;
        }
        float so = o, so2 = o * o;
        #pragma unroll
        for (int off = 16; off > 0; off >>= 1) {
            so  += __shfl_down_sync(0xffffffffu, so,  off);
            so2 += __shfl_down_sync(0xffffffffu, so2, off);
        }
        if (lane == 0) { atomicAdd(&s_stats[j], so); atomicAdd(&s_stats[32 + j], so2); }
    }
    for (int j = 32; j < 56; j++) {
        float o = 0.f;
        if (valid) {
            o = g_num[(size_t)n * IN_DIM + j] * ic + node_attr[(size_t)n * IN_DIM + j];
            staged[(size_t)n * IN_DIM + j] = o;
        }
        float so2 = o * o;
        #pragma unroll
        for (int off = 16; off > 0; off >>= 1)
            so2 += __shfl_down_sync(0xffffffffu, so2, off);
        if (lane == 0) atomicAdd(&s_stats[64 + (j - 32) / 3], so2);
    }
    __syncthreads();
    if (t < 72) atomicAdd(&g_stats[t], s_stats[t]);
}

// ==================================================================
// finalize 2: batch norm in place on d_out
// ==================================================================
__global__ void finalize2_kernel(const float* __restrict__ bn_w_s,
                                 const float* __restrict__ bn_w_v,
                                 const float* __restrict__ bn_b_s,
                                 float* __restrict__ out) {
    const int idx = blockIdx.x * blockDim.x + threadIdx.x;
    if (idx >= N_NODES * IN_DIM) return;
    const int j = idx % IN_DIM;
    const float x = out[idx];
    const float invN = 1.0f / (float)N_NODES;
    if (j < 32) {
        float mean = g_stats[j] * invN;
        float var  = g_stats[32 + j] * invN - mean * mean;
        out[idx] = (x - mean) * rsqrtf(var + 1e-5f) * bn_w_s[j] + bn_b_s[j];
    } else {
        int u = (j - 32) / 3;
        float vn = g_stats[64 + u] * invN * (1.0f / 3.0f);
        out[idx] = x * rsqrtf(vn + 1e-5f) * bn_w_v[u];
    }
}

// ==================================================================
extern "C" void kernel_launch(void* const* d_in, const int* in_sizes, int n_in,
                              void* d_out, int out_size) {
    const float* node_attr  = (const float*)d_in[0];
    const int*   edge_index = (const int*)d_in[1];
    const float* edge_attr  = (const float*)d_in[2];
    const float* edge_sh    = (const float*)d_in[3];
    const float* fc1_w      = (const float*)d_in[4];
    const float* fc1_b      = (const float*)d_in[5];
    const float* fc2_w      = (const float*)d_in[6];
    const float* fc2_b      = (const float*)d_in[7];
    const float* bn_w_s     = (const float*)d_in[8];
    const float* bn_w_v     = (const float*)d_in[9];
    const float* bn_b_s     = (const float*)d_in[10];
    float* out = (float*)d_out;

    static int smem_set = 0;
    if (!smem_set) {
        cudaFuncSetAttribute(gemm2_tp_kernel,
                             cudaFuncAttributeMaxDynamicSharedMemorySize, SMEM_SZ);
        smem_set = 1;
    }

    zero_kernel<<<(N_NODES * IN_DIM + N_NODES + 72 + 255) / 256, 256>>>();
    prepB_kernel<<<(WN_PAD * HIDDEN + 255) / 256, 256>>>(fc2_w);
    {
        dim3 grid(1, M_TILES);
        sgemm1_kernel<<<grid, 256>>>(edge_attr, fc1_w, fc1_b);
    }
    gemm2_tp_kernel<<<M_TILES, 256, SMEM_SZ>>>(node_attr, edge_index, edge_sh, fc2_b);
    finalize1_kernel<<<(N_NODES + 255) / 256, 256>>>(node_attr, out);
    finalize2_kernel<<<(N_NODES * IN_DIM + 255) / 256, 256>>>(bn_w_s, bn_w_v, bn_b_s, out);
}

// round 10
// speedup vs baseline: 2.4516x; 1.2171x over previous
#include <cuda_runtime.h>
#include <cuda_bf16.h>
#include <stdint.h>

#define N_NODES 10000
#define N_EDGES 100000
#define HIDDEN  128
#define WN      1600
#define IN_DIM  56
#define M_TILES 782
#define NT      13

// ---- scratch (static __device__; aligned for cp.async 16B) ----
__device__ __align__(256) __nv_bfloat16 g_Hhi[(size_t)N_EDGES * HIDDEN];
__device__ __align__(256) __nv_bfloat16 g_Hlo[(size_t)N_EDGES * HIDDEN];
__device__ __align__(256) uint4 g_B2pk[NT * 16 * 8 * 32];   // packed B fragments
__device__ __align__(256) float g_num[(size_t)N_NODES * IN_DIM];
__device__ __align__(256) float g_cnt[N_NODES];
__device__ __align__(256) float g_stats[72];

// ==================================================================
// PTX helpers
// ==================================================================
__device__ __forceinline__ uint32_t smem_u32(const void* p) {
    uint32_t a;
    asm("{ .reg .u64 t; cvta.to.shared.u64 t, %1; cvt.u32.u64 %0, t; }"
        : "=r"(a) : "l"(p));
    return a;
}
__device__ __forceinline__ void mma16816(float* c, const uint32_t* a,
                                         uint32_t b0, uint32_t b1) {
    asm volatile(
        "mma.sync.aligned.m16n8k16.row.col.f32.bf16.bf16.f32 "
        "{%0,%1,%2,%3}, {%4,%5,%6,%7}, {%8,%9}, {%0,%1,%2,%3};"
        : "+f"(c[0]), "+f"(c[1]), "+f"(c[2]), "+f"(c[3])
        : "r"(a[0]), "r"(a[1]), "r"(a[2]), "r"(a[3]), "r"(b0), "r"(b1));
}
__device__ __forceinline__ void cp16(uint32_t dst, const void* src) {
    asm volatile("cp.async.cg.shared.global [%0], [%1], 16;" :: "r"(dst), "l"(src));
}
#define CP_COMMIT() asm volatile("cp.async.commit_group;" ::: "memory")
#define CP_WAIT0()  asm volatile("cp.async.wait_group 0;" ::: "memory")
#define CP_WAIT1()  asm volatile("cp.async.wait_group 1;" ::: "memory")

__device__ __forceinline__ void split_pair(float v0, float v1,
                                           uint32_t& hi, uint32_t& lo) {
    __nv_bfloat16 h0 = __float2bfloat16(v0), h1 = __float2bfloat16(v1);
    hi = (uint32_t)__bfloat16_as_ushort(h0)
       | ((uint32_t)__bfloat16_as_ushort(h1) << 16);
    __nv_bfloat16 l0 = __float2bfloat16(v0 - __bfloat162float(h0));
    __nv_bfloat16 l1 = __float2bfloat16(v1 - __bfloat162float(h1));
    lo = (uint32_t)__bfloat16_as_ushort(l0)
       | ((uint32_t)__bfloat16_as_ushort(l1) << 16);
}

// ==================================================================
// zero accumulators (every replay)
// ==================================================================
__global__ void zero_kernel() {
    int i = blockIdx.x * blockDim.x + threadIdx.x;
    const int t0 = N_NODES * IN_DIM;
    const int t1 = t0 + N_NODES;
    const int t2 = t1 + 72;
    if (i < t0)       g_num[i] = 0.f;
    else if (i < t1)  g_cnt[i - t0] = 0.f;
    else if (i < t2)  g_stats[i - t1] = 0.f;
}

// ==================================================================
// pack fc2^T into fragment-major hi/lo uint4s
// idx = ((nt*16 + n8)*8 + ks)*32 + lane
// thread(lane): n = nt*128 + n8*8 + lane/4 ; k = ks*16 + (lane%4)*2
// uint4 = { hi(k,k+1), hi(k+8,k+9), lo(k,k+1), lo(k+8,k+9) }
// ==================================================================
__global__ void prepB_kernel(const float* __restrict__ fc2_w) {
    int idx = blockIdx.x * blockDim.x + threadIdx.x;
    if (idx >= NT * 16 * 8 * 32) return;
    int lane = idx & 31;
    int ks   = (idx >> 5) & 7;
    int n8   = (idx >> 8) & 15;
    int nt   = idx >> 12;
    int n = nt * 128 + n8 * 8 + (lane >> 2);
    int k = ks * 16 + (lane & 3) * 2;
    float v0 = 0.f, v1 = 0.f, v2 = 0.f, v3 = 0.f;
    if (n < WN) {
        v0 = fc2_w[(size_t)k * WN + n];
        v1 = fc2_w[(size_t)(k + 1) * WN + n];
        v2 = fc2_w[(size_t)(k + 8) * WN + n];
        v3 = fc2_w[(size_t)(k + 9) * WN + n];
    }
    uint32_t h01, l01, h23, l23;
    split_pair(v0, v1, h01, l01);
    split_pair(v2, v3, h23, l23);
    g_B2pk[idx] = make_uint4(h01, h23, l01, l23);
}

// ==================================================================
// GEMM1 (fp32): H = relu(edge_attr @ fc1_w + b) -> split bf16 hi/lo
// (unchanged from the 633us passing kernel)
// ==================================================================
__global__ void sgemm1_kernel(const float* __restrict__ A,
                              const float* __restrict__ B,
                              const float* __restrict__ bias) {
    const int M = N_EDGES, N = HIDDEN, K = HIDDEN;
    __shared__ float As[16][132];
    __shared__ float Bs[16][128];

    const int bm = blockIdx.y * 128;
    const int tid = threadIdx.x;
    const int tx = tid & 15, ty = tid >> 4;
    const int row0 = ty * 8, col0 = tx * 8;

    float acc[8][8];
    #pragma unroll
    for (int i = 0; i < 8; i++)
        #pragma unroll
        for (int j = 0; j < 8; j++) acc[i][j] = 0.f;

    for (int k0 = 0; k0 < K; k0 += 16) {
        #pragma unroll
        for (int l = 0; l < 2; l++) {
            int f = tid + l * 256;
            int r = f >> 2, c4 = (f & 3) * 4;
            int gr = bm + r;
            float4 v = make_float4(0.f, 0.f, 0.f, 0.f);
            if (gr < M) v = *reinterpret_cast<const float4*>(&A[(size_t)gr * K + k0 + c4]);
            As[c4 + 0][r] = v.x; As[c4 + 1][r] = v.y;
            As[c4 + 2][r] = v.z; As[c4 + 3][r] = v.w;
        }
        #pragma unroll
        for (int l = 0; l < 2; l++) {
            int f = tid + l * 256;
            int r = f >> 5, c4 = (f & 31) * 4;
            float4 v = *reinterpret_cast<const float4*>(&B[(size_t)(k0 + r) * N + c4]);
            *reinterpret_cast<float4*>(&Bs[r][c4]) = v;
        }
        __syncthreads();
        #pragma unroll
        for (int k = 0; k < 16; k++) {
            float ra[8], rb[8];
            *reinterpret_cast<float4*>(&ra[0]) = *reinterpret_cast<const float4*>(&As[k][row0]);
            *reinterpret_cast<float4*>(&ra[4]) = *reinterpret_cast<const float4*>(&As[k][row0 + 4]);
            *reinterpret_cast<float4*>(&rb[0]) = *reinterpret_cast<const float4*>(&Bs[k][col0]);
            *reinterpret_cast<float4*>(&rb[4]) = *reinterpret_cast<const float4*>(&Bs[k][col0 + 4]);
            #pragma unroll
            for (int i = 0; i < 8; i++)
                #pragma unroll
                for (int j = 0; j < 8; j++) acc[i][j] += ra[i] * rb[j];
        }
        __syncthreads();
    }
    #pragma unroll
    for (int i = 0; i < 8; i++) {
        int gr = bm + row0 + i;
        if (gr >= M) continue;
        #pragma unroll
        for (int j = 0; j < 8; j++) {
            int gc = col0 + j;
            float v = fmaxf(acc[i][j] + bias[gc], 0.f);
            __nv_bfloat16 hi = __float2bfloat16(v);
            __nv_bfloat16 lo = __float2bfloat16(v - __bfloat162float(hi));
            g_Hhi[(size_t)gr * 128 + gc] = hi;
            g_Hlo[(size_t)gr * 128 + gc] = lo;
        }
    }
}

// ==================================================================
// GEMM2 + TP + scatter: 1 CTA = 128 edges, 256 threads (8 warps)
// A fragments hoisted to regs; B tiles = packed LDS.128 fragments,
// cp.async double-buffered.
// ==================================================================
#define SM_B0   0         // 65536: A-hi staging, then even B tiles
#define SM_B1   65536     // 65536: A-lo staging, then odd B tiles
#define A_ST    136       // bf16 elements per staged A row
#define SM_X    131072    // 128 * 62 * 4 = 31744
#define X_ST    62
#define SM_BIAS 162816    // 1664 floats = 6656
#define SMEM_SZ 169472

__global__ void __launch_bounds__(256, 1)
gemm2_tp_kernel(const float* __restrict__ node_attr,
                const int*   __restrict__ edge_index,
                const float* __restrict__ edge_sh,
                const float* __restrict__ fc2_b) {
    extern __shared__ char smem[];
    const uint32_t sb = smem_u32(smem);
    const int tid = threadIdx.x, warp = tid >> 5, lane = tid & 31;
    const int gid = lane >> 2, qid = lane & 3;
    const int bm = blockIdx.x * 128;
    const int lr0 = warp * 16 + gid;

    // ---- stage A (hi -> B0, lo -> B1) ----
    for (int i = tid; i < 2048; i += 256) {
        int r = i >> 4, q = i & 15;
        int gr = bm + r;
        uint32_t doff = (uint32_t)(r * A_ST + q * 8) * 2;
        if (gr < N_EDGES) {
            cp16(sb + SM_B0 + doff, g_Hhi + (size_t)gr * 128 + q * 8);
            cp16(sb + SM_B1 + doff, g_Hlo + (size_t)gr * 128 + q * 8);
        } else {
            *reinterpret_cast<uint4*>(smem + SM_B0 + doff) = make_uint4(0u, 0u, 0u, 0u);
            *reinterpret_cast<uint4*>(smem + SM_B1 + doff) = make_uint4(0u, 0u, 0u, 0u);
        }
    }
    // ---- bias2 ----
    for (int i = tid; i < 416; i += 256) {
        if (i < 400) cp16(sb + SM_BIAS + i * 16, fc2_b + i * 4);
        else *reinterpret_cast<uint4*>(smem + SM_BIAS + i * 16) = make_uint4(0u, 0u, 0u, 0u);
    }
    // ---- per-edge features ----
    float* xss = reinterpret_cast<float*>(smem + SM_X);
    if (tid < 128) {
        const int e = bm + tid;
        const bool valid = (e < N_EDGES);
        float* xr = xss + tid * X_ST;
        int dst = valid ? edge_index[N_EDGES + e] : 0;
        for (int j = 0; j < IN_DIM; j++)
            xr[j] = valid ? node_attr[(size_t)dst * IN_DIM + j] : 0.f;
        float y0 = 0.f, yx = 0.f, yy = 0.f, yz = 0.f;
        int srcn = 0;
        if (valid) {
            srcn = edge_index[e];
            y0 = edge_sh[e * 4 + 0]; yx = edge_sh[e * 4 + 1];
            yy = edge_sh[e * 4 + 2]; yz = edge_sh[e * 4 + 3];
        }
        xr[56] = y0; xr[57] = yx; xr[58] = yy; xr[59] = yz;
        reinterpret_cast<int*>(xr)[60] = srcn;
        reinterpret_cast<int*>(xr)[61] = valid ? 1 : 0;
    }
    CP_COMMIT();
    CP_WAIT0();
    __syncthreads();

    // ---- hoist A fragments (R7-proven indexing) ----
    uint32_t afh[8][4], afl[8][4];
    {
        const __nv_bfloat16* Ah = reinterpret_cast<const __nv_bfloat16*>(smem + SM_B0);
        const __nv_bfloat16* Al = reinterpret_cast<const __nv_bfloat16*>(smem + SM_B1);
        #pragma unroll
        for (int ks = 0; ks < 8; ks++) {
            int c = ks * 16 + qid * 2;
            afh[ks][0] = *reinterpret_cast<const uint32_t*>(Ah + lr0 * A_ST + c);
            afh[ks][1] = *reinterpret_cast<const uint32_t*>(Ah + (lr0 + 8) * A_ST + c);
            afh[ks][2] = *reinterpret_cast<const uint32_t*>(Ah + lr0 * A_ST + c + 8);
            afh[ks][3] = *reinterpret_cast<const uint32_t*>(Ah + (lr0 + 8) * A_ST + c + 8);
            afl[ks][0] = *reinterpret_cast<const uint32_t*>(Al + lr0 * A_ST + c);
            afl[ks][1] = *reinterpret_cast<const uint32_t*>(Al + (lr0 + 8) * A_ST + c);
            afl[ks][2] = *reinterpret_cast<const uint32_t*>(Al + lr0 * A_ST + c + 8);
            afl[ks][3] = *reinterpret_cast<const uint32_t*>(Al + (lr0 + 8) * A_ST + c + 8);
        }
    }
    __syncthreads();   // staging regions now reusable as B tile buffers

    // ---- prefetch packed B tiles 0, 1 ----
    auto loadPK = [&](int nt, uint32_t base) {
        const uint4* srcp = g_B2pk + nt * 4096;
        for (int i = tid; i < 4096; i += 256)
            cp16(base + (uint32_t)i * 16, srcp + i);
    };
    loadPK(0, sb + SM_B0); CP_COMMIT();
    loadPK(1, sb + SM_B1); CP_COMMIT();

    // ---- TP accumulators ----
    float out0[16], out1[12], s1a[4];
    #pragma unroll
    for (int i = 0; i < 16; i++) out0[i] = 0.f;
    #pragma unroll
    for (int i = 0; i < 12; i++) out1[i] = 0.f;
    #pragma unroll
    for (int i = 0; i < 4; i++)  s1a[i] = 0.f;

    const float alpha = 0.15811388300841897f;         // 1/sqrt(40)
    const float cBc   = alpha * 0.57735026918962576f; // alpha/sqrt(3)
    const float* xr0 = xss + lr0 * X_ST;
    const float* xr1 = xss + (lr0 + 8) * X_ST;
    const float* b2s = reinterpret_cast<const float*>(smem + SM_BIAS);

    // epilogue for one 8-col tile (R7-proven branch structure)
    auto epi = [&](int nt, int n8, const float* a) {
        const int coll = n8 * 8 + qid * 2;
        const float bv0 = b2s[nt * 128 + coll], bv1 = b2s[nt * 128 + coll + 1];
        const int gblk = nt * 16 + n8;
        #pragma unroll
        for (int e = 0; e < 2; e++) {
            const float* xr = e ? xr1 : xr0;
            const float v0 = a[e * 2 + 0] + bv0;
            const float v1 = a[e * 2 + 1] + bv1;
            if (gblk < 128) {                        // w00
                const int u = gblk >> 2;
                const float coeff = xr[u] * (alpha * xr[56]);
                const int o = e * 8 + (n8 & 3) * 2;
                out0[o + 0] = fmaf(coeff, v0, out0[o + 0]);
                out0[o + 1] = fmaf(coeff, v1, out0[o + 1]);
            } else if (gblk < 160) {                 // w11
                const int u = (gblk - 128) >> 2;
                const float du = xr[32 + u * 3 + 0] * xr[57]
                               + xr[32 + u * 3 + 1] * xr[58]
                               + xr[32 + u * 3 + 2] * xr[59];
                const float coeff = du * cBc;
                const int o = e * 8 + (n8 & 3) * 2;
                out0[o + 0] = fmaf(coeff, v0, out0[o + 0]);
                out0[o + 1] = fmaf(coeff, v1, out0[o + 1]);
            } else if (gblk < 192) {                 // w01 -> s1
                const float xu = xr[gblk - 160];
                s1a[e * 2 + 0] = fmaf(xu, v0, s1a[e * 2 + 0]);
                s1a[e * 2 + 1] = fmaf(xu, v1, s1a[e * 2 + 1]);
            } else {                                 // w10 -> out1
                const int u = gblk - 192;
                const float cy0 = alpha * xr[56];
                const float x0 = xr[32 + u * 3 + 0] * cy0;
                const float x1 = xr[32 + u * 3 + 1] * cy0;
                const float x2 = xr[32 + u * 3 + 2] * cy0;
                const int o = e * 6;
                out1[o + 0] = fmaf(x0, v0, out1[o + 0]);
                out1[o + 1] = fmaf(x1, v0, out1[o + 1]);
                out1[o + 2] = fmaf(x2, v0, out1[o + 2]);
                out1[o + 3] = fmaf(x0, v1, out1[o + 3]);
                out1[o + 4] = fmaf(x1, v1, out1[o + 4]);
                out1[o + 5] = fmaf(x2, v1, out1[o + 5]);
            }
        }
    };

    // ---- main loop over 13 N-tiles ----
    for (int nt = 0; nt < NT; nt++) {
        CP_WAIT1();
        __syncthreads();
        const uint32_t bufoff = (nt & 1) ? SM_B1 : SM_B0;
        const uint4* bp = reinterpret_cast<const uint4*>(smem + bufoff);
        const int npair = (nt == 12) ? 4 : 8;       // cols >= 1600 are padding

        for (int p = 0; p < npair; p++) {
            float a0[4] = {0.f, 0.f, 0.f, 0.f};
            float a1[4] = {0.f, 0.f, 0.f, 0.f};
            const uint4* f0p = bp + (2 * p) * 256 + lane;       // (n8*8+ks)*32+lane
            const uint4* f1p = bp + (2 * p + 1) * 256 + lane;
            #pragma unroll
            for (int ks = 0; ks < 8; ks++) {
                const uint4 f0 = f0p[ks * 32];
                const uint4 f1 = f1p[ks * 32];
                mma16816(a0, afh[ks], f0.x, f0.y);
                mma16816(a1, afh[ks], f1.x, f1.y);
                mma16816(a0, afh[ks], f0.z, f0.w);
                mma16816(a1, afh[ks], f1.z, f1.w);
                mma16816(a0, afl[ks], f0.x, f0.y);
                mma16816(a1, afl[ks], f1.x, f1.y);
            }
            epi(nt, 2 * p,     a0);
            epi(nt, 2 * p + 1, a1);
        }
        __syncthreads();                 // buffer fully consumed
        if (nt + 2 < NT) loadPK(nt + 2, sb + bufoff);
        CP_COMMIT();                     // commit every iteration
    }

    // ---- fold w01 path, scatter ----
    #pragma unroll
    for (int e = 0; e < 2; e++) {
        const float* xr = e ? xr1 : xr0;
        if (!reinterpret_cast<const int*>(xr)[61]) continue;
        const int srcn = reinterpret_cast<const int*>(xr)[60];
        const float yx = xr[57], yy = xr[58], yz = xr[59];
        #pragma unroll
        for (int p = 0; p < 2; p++) {
            const float sw = s1a[e * 2 + p] * alpha;
            out1[e * 6 + p * 3 + 0] = fmaf(sw, yx, out1[e * 6 + p * 3 + 0]);
            out1[e * 6 + p * 3 + 1] = fmaf(sw, yy, out1[e * 6 + p * 3 + 1]);
            out1[e * 6 + p * 3 + 2] = fmaf(sw, yz, out1[e * 6 + p * 3 + 2]);
        }
        float* dstp = g_num + (size_t)srcn * IN_DIM;
        #pragma unroll
        for (int q = 0; q < 4; q++)
            #pragma unroll
            for (int p = 0; p < 2; p++) {
                const int w = q * 8 + qid * 2 + p;
                atomicAdd(&dstp[w], out0[e * 8 + q * 2 + p]);
            }
        #pragma unroll
        for (int p = 0; p < 2; p++) {
            const int w8 = qid * 2 + p;
            atomicAdd(&dstp[32 + w8 * 3 + 0], out1[e * 6 + p * 3 + 0]);
            atomicAdd(&dstp[32 + w8 * 3 + 1], out1[e * 6 + p * 3 + 1]);
            atomicAdd(&dstp[32 + w8 * 3 + 2], out1[e * 6 + p * 3 + 2]);
        }
        if (qid == 0) atomicAdd(&g_cnt[srcn], 1.0f);
    }
}

// ==================================================================
// finalize 1: out_pre = num/max(cnt,1) + node_attr, accumulate BN stats
// ==================================================================
__global__ void finalize1_kernel(const float* __restrict__ node_attr,
                                 float* __restrict__ staged) {
    __shared__ float s_stats[72];
    const int t = threadIdx.x;
    if (t < 72) s_stats[t] = 0.f;
    __syncthreads();

    const int n = blockIdx.x * blockDim.x + t;
    const bool valid = (n < N_NODES);
    float ic = 0.f;
    if (valid) ic = 1.f / fmaxf(g_cnt[n], 1.f);
    const int lane = t & 31;

    for (int j = 0; j < 32; j++) {
        float o = 0.f;
        if (valid) {
            o = g_num[(size_t)n * IN_DIM + j] * ic + node_attr[(size_t)n * IN_DIM + j];
            staged[(size_t)n * IN_DIM + j] = o;
        }
        float so = o, so2 = o * o;
        #pragma unroll
        for (int off = 16; off > 0; off >>= 1) {
            so  += __shfl_down_sync(0xffffffffu, so,  off);
            so2 += __shfl_down_sync(0xffffffffu, so2, off);
        }
        if (lane == 0) { atomicAdd(&s_stats[j], so); atomicAdd(&s_stats[32 + j], so2); }
    }
    for (int j = 32; j < 56; j++) {
        float o = 0.f;
        if (valid) {
            o = g_num[(size_t)n * IN_DIM + j] * ic + node_attr[(size_t)n * IN_DIM + j];
            staged[(size_t)n * IN_DIM + j] = o;
        }
        float so2 = o * o;
        #pragma unroll
        for (int off = 16; off > 0; off >>= 1)
            so2 += __shfl_down_sync(0xffffffffu, so2, off);
        if (lane == 0) atomicAdd(&s_stats[64 + (j - 32) / 3], so2);
    }
    __syncthreads();
    if (t < 72) atomicAdd(&g_stats[t], s_stats[t]);
}

// ==================================================================
// finalize 2: batch norm in place on d_out
// ==================================================================
__global__ void finalize2_kernel(const float* __restrict__ bn_w_s,
                                 const float* __restrict__ bn_w_v,
                                 const float* __restrict__ bn_b_s,
                                 float* __restrict__ out) {
    const int idx = blockIdx.x * blockDim.x + threadIdx.x;
    if (idx >= N_NODES * IN_DIM) return;
    const int j = idx % IN_DIM;
    const float x = out[idx];
    const float invN = 1.0f / (float)N_NODES;
    if (j < 32) {
        float mean = g_stats[j] * invN;
        float var  = g_stats[32 + j] * invN - mean * mean;
        out[idx] = (x - mean) * rsqrtf(var + 1e-5f) * bn_w_s[j] + bn_b_s[j];
    } else {
        int u = (j - 32) / 3;
        float vn = g_stats[64 + u] * invN * (1.0f / 3.0f);
        out[idx] = x * rsqrtf(vn + 1e-5f) * bn_w_v[u];
    }
}

// ==================================================================
extern "C" void kernel_launch(void* const* d_in, const int* in_sizes, int n_in,
                              void* d_out, int out_size) {
    const float* node_attr  = (const float*)d_in[0];
    const int*   edge_index = (const int*)d_in[1];
    const float* edge_attr  = (const float*)d_in[2];
    const float* edge_sh    = (const float*)d_in[3];
    const float* fc1_w      = (const float*)d_in[4];
    const float* fc1_b      = (const float*)d_in[5];
    const float* fc2_w      = (const float*)d_in[6];
    const float* fc2_b      = (const float*)d_in[7];
    const float* bn_w_s     = (const float*)d_in[8];
    const float* bn_w_v     = (const float*)d_in[9];
    const float* bn_b_s     = (const float*)d_in[10];
    float* out = (float*)d_out;

    cudaFuncSetAttribute(gemm2_tp_kernel,
                         cudaFuncAttributeMaxDynamicSharedMemorySize, SMEM_SZ);

    zero_kernel<<<(N_NODES * IN_DIM + N_NODES + 72 + 255) / 256, 256>>>();
    prepB_kernel<<<(NT * 16 * 8 * 32 + 255) / 256, 256>>>(fc2_w);
    {
        dim3 grid(1, M_TILES);
        sgemm1_kernel<<<grid, 256>>>(edge_attr, fc1_w, fc1_b);
    }
    gemm2_tp_kernel<<<M_TILES, 256, SMEM_SZ>>>(node_attr, edge_index, edge_sh, fc2_b);
    finalize1_kernel<<<(N_NODES + 255) / 256, 256>>>(node_attr, out);
    finalize2_kernel<<<(N_NODES * IN_DIM + 255) / 256, 256>>>(bn_w_s, bn_w_v, bn_b_s, out);
}

// round 11
// speedup vs baseline: 2.5429x; 1.0373x over previous
#include <cuda_runtime.h>
#include <cuda_bf16.h>
#include <stdint.h>

#define N_NODES 10000
#define N_EDGES 100000
#define HIDDEN  128
#define WN      1600
#define IN_DIM  56
#define NT      13
#define EPC     256                       // edges per CTA
#define M_TILES2 ((N_EDGES + EPC - 1) / EPC)   // 391
#define M_TILES1 ((N_EDGES + 127) / 128)       // 782 (gemm1)

// ---- scratch (static __device__; aligned for cp.async 16B) ----
__device__ __align__(256) __nv_bfloat16 g_Hhi[(size_t)N_EDGES * HIDDEN];
__device__ __align__(256) __nv_bfloat16 g_Hlo[(size_t)N_EDGES * HIDDEN];
__device__ __align__(256) uint4 g_B2pk[NT * 16 * 8 * 32];   // packed B fragments
__device__ __align__(256) float g_num[(size_t)N_NODES * IN_DIM];
__device__ __align__(256) float g_cnt[N_NODES];
__device__ __align__(256) float g_stats[72];

// ==================================================================
// PTX helpers
// ==================================================================
__device__ __forceinline__ uint32_t smem_u32(const void* p) {
    uint32_t a;
    asm("{ .reg .u64 t; cvta.to.shared.u64 t, %1; cvt.u32.u64 %0, t; }"
        : "=r"(a) : "l"(p));
    return a;
}
__device__ __forceinline__ void mma16816(float* c, const uint32_t* a,
                                         uint32_t b0, uint32_t b1) {
    asm volatile(
        "mma.sync.aligned.m16n8k16.row.col.f32.bf16.bf16.f32 "
        "{%0,%1,%2,%3}, {%4,%5,%6,%7}, {%8,%9}, {%0,%1,%2,%3};"
        : "+f"(c[0]), "+f"(c[1]), "+f"(c[2]), "+f"(c[3])
        : "r"(a[0]), "r"(a[1]), "r"(a[2]), "r"(a[3]), "r"(b0), "r"(b1));
}
__device__ __forceinline__ void cp16(uint32_t dst, const void* src) {
    asm volatile("cp.async.cg.shared.global [%0], [%1], 16;" :: "r"(dst), "l"(src));
}
#define CP_COMMIT() asm volatile("cp.async.commit_group;" ::: "memory")
#define CP_WAIT0()  asm volatile("cp.async.wait_group 0;" ::: "memory")
#define CP_WAIT1()  asm volatile("cp.async.wait_group 1;" ::: "memory")

__device__ __forceinline__ void split_pair(float v0, float v1,
                                           uint32_t& hi, uint32_t& lo) {
    __nv_bfloat16 h0 = __float2bfloat16(v0), h1 = __float2bfloat16(v1);
    hi = (uint32_t)__bfloat16_as_ushort(h0)
       | ((uint32_t)__bfloat16_as_ushort(h1) << 16);
    __nv_bfloat16 l0 = __float2bfloat16(v0 - __bfloat162float(h0));
    __nv_bfloat16 l1 = __float2bfloat16(v1 - __bfloat162float(h1));
    lo = (uint32_t)__bfloat16_as_ushort(l0)
       | ((uint32_t)__bfloat16_as_ushort(l1) << 16);
}

// ==================================================================
// zero accumulators (every replay)
// ==================================================================
__global__ void zero_kernel() {
    int i = blockIdx.x * blockDim.x + threadIdx.x;
    const int t0 = N_NODES * IN_DIM;
    const int t1 = t0 + N_NODES;
    const int t2 = t1 + 72;
    if (i < t0)       g_num[i] = 0.f;
    else if (i < t1)  g_cnt[i - t0] = 0.f;
    else if (i < t2)  g_stats[i - t1] = 0.f;
}

// ==================================================================
// pack fc2^T into fragment-major hi/lo uint4s (unchanged, proven)
// ==================================================================
__global__ void prepB_kernel(const float* __restrict__ fc2_w) {
    int idx = blockIdx.x * blockDim.x + threadIdx.x;
    if (idx >= NT * 16 * 8 * 32) return;
    int lane = idx & 31;
    int ks   = (idx >> 5) & 7;
    int n8   = (idx >> 8) & 15;
    int nt   = idx >> 12;
    int n = nt * 128 + n8 * 8 + (lane >> 2);
    int k = ks * 16 + (lane & 3) * 2;
    float v0 = 0.f, v1 = 0.f, v2 = 0.f, v3 = 0.f;
    if (n < WN) {
        v0 = fc2_w[(size_t)k * WN + n];
        v1 = fc2_w[(size_t)(k + 1) * WN + n];
        v2 = fc2_w[(size_t)(k + 8) * WN + n];
        v3 = fc2_w[(size_t)(k + 9) * WN + n];
    }
    uint32_t h01, l01, h23, l23;
    split_pair(v0, v1, h01, l01);
    split_pair(v2, v3, h23, l23);
    g_B2pk[idx] = make_uint4(h01, h23, l01, l23);
}

// ==================================================================
// GEMM1 (fp32): H = relu(edge_attr @ fc1_w + b) -> split bf16 hi/lo
// (unchanged, proven)
// ==================================================================
__global__ void sgemm1_kernel(const float* __restrict__ A,
                              const float* __restrict__ B,
                              const float* __restrict__ bias) {
    const int M = N_EDGES, N = HIDDEN, K = HIDDEN;
    __shared__ float As[16][132];
    __shared__ float Bs[16][128];

    const int bm = blockIdx.y * 128;
    const int tid = threadIdx.x;
    const int tx = tid & 15, ty = tid >> 4;
    const int row0 = ty * 8, col0 = tx * 8;

    float acc[8][8];
    #pragma unroll
    for (int i = 0; i < 8; i++)
        #pragma unroll
        for (int j = 0; j < 8; j++) acc[i][j] = 0.f;

    for (int k0 = 0; k0 < K; k0 += 16) {
        #pragma unroll
        for (int l = 0; l < 2; l++) {
            int f = tid + l * 256;
            int r = f >> 2, c4 = (f & 3) * 4;
            int gr = bm + r;
            float4 v = make_float4(0.f, 0.f, 0.f, 0.f);
            if (gr < M) v = *reinterpret_cast<const float4*>(&A[(size_t)gr * K + k0 + c4]);
            As[c4 + 0][r] = v.x; As[c4 + 1][r] = v.y;
            As[c4 + 2][r] = v.z; As[c4 + 3][r] = v.w;
        }
        #pragma unroll
        for (int l = 0; l < 2; l++) {
            int f = tid + l * 256;
            int r = f >> 5, c4 = (f & 31) * 4;
            float4 v = *reinterpret_cast<const float4*>(&B[(size_t)(k0 + r) * N + c4]);
            *reinterpret_cast<float4*>(&Bs[r][c4]) = v;
        }
        __syncthreads();
        #pragma unroll
        for (int k = 0; k < 16; k++) {
            float ra[8], rb[8];
            *reinterpret_cast<float4*>(&ra[0]) = *reinterpret_cast<const float4*>(&As[k][row0]);
            *reinterpret_cast<float4*>(&ra[4]) = *reinterpret_cast<const float4*>(&As[k][row0 + 4]);
            *reinterpret_cast<float4*>(&rb[0]) = *reinterpret_cast<const float4*>(&Bs[k][col0]);
            *reinterpret_cast<float4*>(&rb[4]) = *reinterpret_cast<const float4*>(&Bs[k][col0 + 4]);
            #pragma unroll
            for (int i = 0; i < 8; i++)
                #pragma unroll
                for (int j = 0; j < 8; j++) acc[i][j] += ra[i] * rb[j];
        }
        __syncthreads();
    }
    #pragma unroll
    for (int i = 0; i < 8; i++) {
        int gr = bm + row0 + i;
        if (gr >= M) continue;
        #pragma unroll
        for (int j = 0; j < 8; j++) {
            int gc = col0 + j;
            float v = fmaxf(acc[i][j] + bias[gc], 0.f);
            __nv_bfloat16 hi = __float2bfloat16(v);
            __nv_bfloat16 lo = __float2bfloat16(v - __bfloat162float(hi));
            g_Hhi[(size_t)gr * 128 + gc] = hi;
            g_Hlo[(size_t)gr * 128 + gc] = lo;
        }
    }
}

// ==================================================================
// GEMM2 + TP + scatter: 1 CTA = 256 edges, 512 threads (16 warps)
// 4 warps/SMSP for MMA latency hiding; B tiles cp.async double-buffered.
// ==================================================================
#define SM_B0   0         // 65536: A-hi staging, then even B tiles
#define SM_B1   65536     // 65536: A-lo staging, then odd B tiles
#define A_ST    128       // bf16 elements per staged A row (exact fit)
#define SM_X    131072    // 256 * 62 * 4 = 63488
#define X_ST    62
#define SM_BIAS 194560    // 416 uint4 = 6656
#define SMEM_SZ 201216

__global__ void __launch_bounds__(512, 1)
gemm2_tp_kernel(const float* __restrict__ node_attr,
                const int*   __restrict__ edge_index,
                const float* __restrict__ edge_sh,
                const float* __restrict__ fc2_b) {
    extern __shared__ char smem[];
    const uint32_t sb = smem_u32(smem);
    const int tid = threadIdx.x, warp = tid >> 5, lane = tid & 31;
    const int gid = lane >> 2, qid = lane & 3;
    const int bm = blockIdx.x * EPC;
    const int lr0 = warp * 16 + gid;          // 0..255

    // ---- stage A (hi -> B0, lo -> B1), 256 rows x 128 cols bf16 ----
    for (int i = tid; i < 4096; i += 512) {
        int r = i >> 4, q = i & 15;
        int gr = bm + r;
        uint32_t doff = (uint32_t)(r * A_ST + q * 8) * 2;
        if (gr < N_EDGES) {
            cp16(sb + SM_B0 + doff, g_Hhi + (size_t)gr * 128 + q * 8);
            cp16(sb + SM_B1 + doff, g_Hlo + (size_t)gr * 128 + q * 8);
        } else {
            *reinterpret_cast<uint4*>(smem + SM_B0 + doff) = make_uint4(0u, 0u, 0u, 0u);
            *reinterpret_cast<uint4*>(smem + SM_B1 + doff) = make_uint4(0u, 0u, 0u, 0u);
        }
    }
    // ---- bias2 ----
    for (int i = tid; i < 416; i += 512) {
        if (i < 400) cp16(sb + SM_BIAS + i * 16, fc2_b + i * 4);
        else *reinterpret_cast<uint4*>(smem + SM_BIAS + i * 16) = make_uint4(0u, 0u, 0u, 0u);
    }
    // ---- per-edge features ----
    float* xss = reinterpret_cast<float*>(smem + SM_X);
    if (tid < EPC) {
        const int e = bm + tid;
        const bool valid = (e < N_EDGES);
        float* xr = xss + tid * X_ST;
        int dst = valid ? edge_index[N_EDGES + e] : 0;
        for (int j = 0; j < IN_DIM; j++)
            xr[j] = valid ? node_attr[(size_t)dst * IN_DIM + j] : 0.f;
        float y0 = 0.f, yx = 0.f, yy = 0.f, yz = 0.f;
        int srcn = 0;
        if (valid) {
            srcn = edge_index[e];
            y0 = edge_sh[e * 4 + 0]; yx = edge_sh[e * 4 + 1];
            yy = edge_sh[e * 4 + 2]; yz = edge_sh[e * 4 + 3];
        }
        xr[56] = y0; xr[57] = yx; xr[58] = yy; xr[59] = yz;
        reinterpret_cast<int*>(xr)[60] = srcn;
        reinterpret_cast<int*>(xr)[61] = valid ? 1 : 0;
    }
    CP_COMMIT();
    CP_WAIT0();
    __syncthreads();

    // ---- hoist A fragments (proven indexing; one-time LDS) ----
    uint32_t afh[8][4], afl[8][4];
    {
        const __nv_bfloat16* Ah = reinterpret_cast<const __nv_bfloat16*>(smem + SM_B0);
        const __nv_bfloat16* Al = reinterpret_cast<const __nv_bfloat16*>(smem + SM_B1);
        #pragma unroll
        for (int ks = 0; ks < 8; ks++) {
            int c = ks * 16 + qid * 2;
            afh[ks][0] = *reinterpret_cast<const uint32_t*>(Ah + lr0 * A_ST + c);
            afh[ks][1] = *reinterpret_cast<const uint32_t*>(Ah + (lr0 + 8) * A_ST + c);
            afh[ks][2] = *reinterpret_cast<const uint32_t*>(Ah + lr0 * A_ST + c + 8);
            afh[ks][3] = *reinterpret_cast<const uint32_t*>(Ah + (lr0 + 8) * A_ST + c + 8);
            afl[ks][0] = *reinterpret_cast<const uint32_t*>(Al + lr0 * A_ST + c);
            afl[ks][1] = *reinterpret_cast<const uint32_t*>(Al + (lr0 + 8) * A_ST + c);
            afl[ks][2] = *reinterpret_cast<const uint32_t*>(Al + lr0 * A_ST + c + 8);
            afl[ks][3] = *reinterpret_cast<const uint32_t*>(Al + (lr0 + 8) * A_ST + c + 8);
        }
    }
    __syncthreads();   // staging regions now reusable as B tile buffers

    // ---- prefetch packed B tiles 0, 1 ----
    auto loadPK = [&](int nt, uint32_t base) {
        const uint4* srcp = g_B2pk + nt * 4096;
        for (int i = tid; i < 4096; i += 512)
            cp16(base + (uint32_t)i * 16, srcp + i);
    };
    loadPK(0, sb + SM_B0); CP_COMMIT();
    loadPK(1, sb + SM_B1); CP_COMMIT();

    // ---- TP accumulators ----
    float out0[16], out1[12], s1a[4];
    #pragma unroll
    for (int i = 0; i < 16; i++) out0[i] = 0.f;
    #pragma unroll
    for (int i = 0; i < 12; i++) out1[i] = 0.f;
    #pragma unroll
    for (int i = 0; i < 4; i++)  s1a[i] = 0.f;

    const float alpha = 0.15811388300841897f;         // 1/sqrt(40)
    const float cBc   = alpha * 0.57735026918962576f; // alpha/sqrt(3)
    const float* xr0 = xss + lr0 * X_ST;
    const float* xr1 = xss + (lr0 + 8) * X_ST;
    const float* b2s = reinterpret_cast<const float*>(smem + SM_BIAS);

    // epilogue for one 8-col tile (proven branch structure)
    auto epi = [&](int nt, int n8, const float* a) {
        const int coll = n8 * 8 + qid * 2;
        const float bv0 = b2s[nt * 128 + coll], bv1 = b2s[nt * 128 + coll + 1];
        const int gblk = nt * 16 + n8;
        #pragma unroll
        for (int e = 0; e < 2; e++) {
            const float* xr = e ? xr1 : xr0;
            const float v0 = a[e * 2 + 0] + bv0;
            const float v1 = a[e * 2 + 1] + bv1;
            if (gblk < 128) {                        // w00
                const int u = gblk >> 2;
                const float coeff = xr[u] * (alpha * xr[56]);
                const int o = e * 8 + (n8 & 3) * 2;
                out0[o + 0] = fmaf(coeff, v0, out0[o + 0]);
                out0[o + 1] = fmaf(coeff, v1, out0[o + 1]);
            } else if (gblk < 160) {                 // w11
                const int u = (gblk - 128) >> 2;
                const float du = xr[32 + u * 3 + 0] * xr[57]
                               + xr[32 + u * 3 + 1] * xr[58]
                               + xr[32 + u * 3 + 2] * xr[59];
                const float coeff = du * cBc;
                const int o = e * 8 + (n8 & 3) * 2;
                out0[o + 0] = fmaf(coeff, v0, out0[o + 0]);
                out0[o + 1] = fmaf(coeff, v1, out0[o + 1]);
            } else if (gblk < 192) {                 // w01 -> s1
                const float xu = xr[gblk - 160];
                s1a[e * 2 + 0] = fmaf(xu, v0, s1a[e * 2 + 0]);
                s1a[e * 2 + 1] = fmaf(xu, v1, s1a[e * 2 + 1]);
            } else {                                 // w10 -> out1
                const int u = gblk - 192;
                const float cy0 = alpha * xr[56];
                const float x0 = xr[32 + u * 3 + 0] * cy0;
                const float x1 = xr[32 + u * 3 + 1] * cy0;
                const float x2 = xr[32 + u * 3 + 2] * cy0;
                const int o = e * 6;
                out1[o + 0] = fmaf(x0, v0, out1[o + 0]);
                out1[o + 1] = fmaf(x1, v0, out1[o + 1]);
                out1[o + 2] = fmaf(x2, v0, out1[o + 2]);
                out1[o + 3] = fmaf(x0, v1, out1[o + 3]);
                out1[o + 4] = fmaf(x1, v1, out1[o + 4]);
                out1[o + 5] = fmaf(x2, v1, out1[o + 5]);
            }
        }
    };

    // ---- main loop over 13 N-tiles ----
    for (int nt = 0; nt < NT; nt++) {
        CP_WAIT1();
        __syncthreads();
        const uint32_t bufoff = (nt & 1) ? SM_B1 : SM_B0;
        const uint4* bp = reinterpret_cast<const uint4*>(smem + bufoff);
        const int npair = (nt == 12) ? 4 : 8;       // cols >= 1600 are padding

        for (int p = 0; p < npair; p++) {
            float a0[4] = {0.f, 0.f, 0.f, 0.f};
            float a1[4] = {0.f, 0.f, 0.f, 0.f};
            const uint4* f0p = bp + (2 * p) * 256 + lane;       // (n8*8+ks)*32+lane
            const uint4* f1p = bp + (2 * p + 1) * 256 + lane;
            #pragma unroll
            for (int ks = 0; ks < 8; ks++) {
                const uint4 f0 = f0p[ks * 32];
                const uint4 f1 = f1p[ks * 32];
                mma16816(a0, afh[ks], f0.x, f0.y);
                mma16816(a1, afh[ks], f1.x, f1.y);
                mma16816(a0, afh[ks], f0.z, f0.w);
                mma16816(a1, afh[ks], f1.z, f1.w);
                mma16816(a0, afl[ks], f0.x, f0.y);
                mma16816(a1, afl[ks], f1.x, f1.y);
            }
            epi(nt, 2 * p,     a0);
            epi(nt, 2 * p + 1, a1);
        }
        __syncthreads();                 // buffer fully consumed
        if (nt + 2 < NT) loadPK(nt + 2, sb + bufoff);
        CP_COMMIT();                     // commit every iteration
    }

    // ---- fold w01 path, scatter ----
    #pragma unroll
    for (int e = 0; e < 2; e++) {
        const float* xr = e ? xr1 : xr0;
        if (!reinterpret_cast<const int*>(xr)[61]) continue;
        const int srcn = reinterpret_cast<const int*>(xr)[60];
        const float yx = xr[57], yy = xr[58], yz = xr[59];
        #pragma unroll
        for (int p = 0; p < 2; p++) {
            const float sw = s1a[e * 2 + p] * alpha;
            out1[e * 6 + p * 3 + 0] = fmaf(sw, yx, out1[e * 6 + p * 3 + 0]);
            out1[e * 6 + p * 3 + 1] = fmaf(sw, yy, out1[e * 6 + p * 3 + 1]);
            out1[e * 6 + p * 3 + 2] = fmaf(sw, yz, out1[e * 6 + p * 3 + 2]);
        }
        float* dstp = g_num + (size_t)srcn * IN_DIM;
        #pragma unroll
        for (int q = 0; q < 4; q++)
            #pragma unroll
            for (int p = 0; p < 2; p++) {
                const int w = q * 8 + qid * 2 + p;
                atomicAdd(&dstp[w], out0[e * 8 + q * 2 + p]);
            }
        #pragma unroll
        for (int p = 0; p < 2; p++) {
            const int w8 = qid * 2 + p;
            atomicAdd(&dstp[32 + w8 * 3 + 0], out1[e * 6 + p * 3 + 0]);
            atomicAdd(&dstp[32 + w8 * 3 + 1], out1[e * 6 + p * 3 + 1]);
            atomicAdd(&dstp[32 + w8 * 3 + 2], out1[e * 6 + p * 3 + 2]);
        }
        if (qid == 0) atomicAdd(&g_cnt[srcn], 1.0f);
    }
}

// ==================================================================
// finalize 1: out_pre = num/max(cnt,1) + node_attr, accumulate BN stats
// ==================================================================
__global__ void finalize1_kernel(const float* __restrict__ node_attr,
                                 float* __restrict__ staged) {
    __shared__ float s_stats[72];
    const int t = threadIdx.x;
    if (t < 72) s_stats[t] = 0.f;
    __syncthreads();

    const int n = blockIdx.x * blockDim.x + t;
    const bool valid = (n < N_NODES);
    float ic = 0.f;
    if (valid) ic = 1.f / fmaxf(g_cnt[n], 1.f);
    const int lane = t & 31;

    for (int j = 0; j < 32; j++) {
        float o = 0.f;
        if (valid) {
            o = g_num[(size_t)n * IN_DIM + j] * ic + node_attr[(size_t)n * IN_DIM + j];
            staged[(size_t)n * IN_DIM + j] = o;
        }
        float so = o, so2 = o * o;
        #pragma unroll
        for (int off = 16; off > 0; off >>= 1) {
            so  += __shfl_down_sync(0xffffffffu, so,  off);
            so2 += __shfl_down_sync(0xffffffffu, so2, off);
        }
        if (lane == 0) { atomicAdd(&s_stats[j], so); atomicAdd(&s_stats[32 + j], so2); }
    }
    for (int j = 32; j < 56; j++) {
        float o = 0.f;
        if (valid) {
            o = g_num[(size_t)n * IN_DIM + j] * ic + node_attr[(size_t)n * IN_DIM + j];
            staged[(size_t)n * IN_DIM + j] = o;
        }
        float so2 = o * o;
        #pragma unroll
        for (int off = 16; off > 0; off >>= 1)
            so2 += __shfl_down_sync(0xffffffffu, so2, off);
        if (lane == 0) atomicAdd(&s_stats[64 + (j - 32) / 3], so2);
    }
    __syncthreads();
    if (t < 72) atomicAdd(&g_stats[t], s_stats[t]);
}

// ==================================================================
// finalize 2: batch norm in place on d_out
// ==================================================================
__global__ void finalize2_kernel(const float* __restrict__ bn_w_s,
                                 const float* __restrict__ bn_w_v,
                                 const float* __restrict__ bn_b_s,
                                 float* __restrict__ out) {
    const int idx = blockIdx.x * blockDim.x + threadIdx.x;
    if (idx >= N_NODES * IN_DIM) return;
    const int j = idx % IN_DIM;
    const float x = out[idx];
    const float invN = 1.0f / (float)N_NODES;
    if (j < 32) {
        float mean = g_stats[j] * invN;
        float var  = g_stats[32 + j] * invN - mean * mean;
        out[idx] = (x - mean) * rsqrtf(var + 1e-5f) * bn_w_s[j] + bn_b_s[j];
    } else {
        int u = (j - 32) / 3;
        float vn = g_stats[64 + u] * invN * (1.0f / 3.0f);
        out[idx] = x * rsqrtf(vn + 1e-5f) * bn_w_v[u];
    }
}

// ==================================================================
extern "C" void kernel_launch(void* const* d_in, const int* in_sizes, int n_in,
                              void* d_out, int out_size) {
    const float* node_attr  = (const float*)d_in[0];
    const int*   edge_index = (const int*)d_in[1];
    const float* edge_attr  = (const float*)d_in[2];
    const float* edge_sh    = (const float*)d_in[3];
    const float* fc1_w      = (const float*)d_in[4];
    const float* fc1_b      = (const float*)d_in[5];
    const float* fc2_w      = (const float*)d_in[6];
    const float* fc2_b      = (const float*)d_in[7];
    const float* bn_w_s     = (const float*)d_in[8];
    const float* bn_w_v     = (const float*)d_in[9];
    const float* bn_b_s     = (const float*)d_in[10];
    float* out = (float*)d_out;

    cudaFuncSetAttribute(gemm2_tp_kernel,
                         cudaFuncAttributeMaxDynamicSharedMemorySize, SMEM_SZ);

    zero_kernel<<<(N_NODES * IN_DIM + N_NODES + 72 + 255) / 256, 256>>>();
    prepB_kernel<<<(NT * 16 * 8 * 32 + 255) / 256, 256>>>(fc2_w);
    {
        dim3 grid(1, M_TILES1);
        sgemm1_kernel<<<grid, 256>>>(edge_attr, fc1_w, fc1_b);
    }
    gemm2_tp_kernel<<<M_TILES2, 512, SMEM_SZ>>>(node_attr, edge_index, edge_sh, fc2_b);
    finalize1_kernel<<<(N_NODES + 255) / 256, 256>>>(node_attr, out);
    finalize2_kernel<<<(N_NODES * IN_DIM + 255) / 256, 256>>>(bn_w_s, bn_w_v, bn_b_s, out);
}